// round 16
// baseline (speedup 1.0000x reference)
#include <cuda_runtime.h>
#include <cuda_fp16.h>
#include <cstdint>

#define N_NODES 100000
#define N_EDGES 1600000
#define FEAT 64
#define TPB 256
#define NBLK 592                              // 148 SMs x 4 blocks, co-resident
#define NTILE ((N_NODES + 63) / 64)           // 1563 gemm tiles
#define NE4 (N_EDGES / 4)                     // 400000
#define NRG2 (N_NODES / 16)                   // 6250 row-pair groups
#define NH2 (N_NODES * 32)                    // half2 words in H

#define SCAN_PT 16
#define SCAN_CHUNK (TPB * SCAN_PT)            // 4096
#define SCAN_NBLOCKS ((N_NODES + SCAN_CHUNK - 1) / SCAN_CHUNK)   // 25
#define FLAG_VALID (1 << 30)
#define FLAG_MASK  (FLAG_VALID - 1)

// ---------------- scratch (static device globals: allocation-free) ----------
// H' = dinv * (X@W), fp16, ONE zero pad row at index N_NODES.
__device__ __half g_H[(N_NODES + 1) * FEAT];
__device__ __half g_Ah[N_NODES * FEAT];       // activations, fp16 storage
__device__ float  g_dinv[N_NODES];
__device__ int    g_rowstart[N_NODES + 1];
__device__ int    g_cursor[N_NODES];
__device__ int    g_csrsrc[N_EDGES];          // src-only CSR (norm folded into H')
__device__ int    g_zr[N_NODES + 64];         // deg + lookback flags (one memset)
__device__ unsigned g_barTicket = 0;          // monotone grid barrier (replay-safe)

__device__ __forceinline__ uint32_t smem_u32(const void* p) {
    return (uint32_t)__cvta_generic_to_shared(p);
}

__device__ __forceinline__ void cp16(uint32_t dst, const void* src) {
    asm volatile("cp.async.cg.shared.global [%0], [%1], 16;"
                 :: "r"(dst), "l"(src) : "memory");
}

// ---- grid-wide barrier ----
__device__ __forceinline__ void grid_barrier() {
    __syncthreads();
    if (threadIdx.x == 0) {
        __threadfence();
        unsigned old = atomicAdd(&g_barTicket, 1u);
        unsigned target = (old / NBLK + 1u) * NBLK;
        while (atomicAdd(&g_barTicket, 0u) < target) __nanosleep(64);
        __threadfence();
    }
    __syncthreads();
}

// ---------------- tensor-core gemm ---------------------------------------------
template<int XKIND, int DINV>
__device__ __forceinline__ void gemm_phase_mma(const void* Xv,
                                               const float* __restrict__ W,
                                               int tid, int bid,
                                               __half (*Xs)[72], __half (*Wh)[72]) {
    {
        const float4* W4 = (const float4*)W;
        #pragma unroll
        for (int i = 0; i < 4; i++) {
            int li = tid + 256 * i;
            int r = li >> 4, c4 = (li & 15) * 4;
            float4 w = W4[li];
            *(__half2*)&Wh[r][c4]     = __floats2half2_rn(w.x, w.y);
            *(__half2*)&Wh[r][c4 + 2] = __floats2half2_rn(w.z, w.w);
        }
    }
    int lane = tid & 31, w8 = tid >> 5;
    int rt = w8 & 3;
    int ch = w8 >> 2;

    for (int t = bid; t < NTILE; t += NBLK) {
        int row0 = t * 64;
        #pragma unroll
        for (int i = 0; i < 4; i++) {
            int li = tid + 256 * i;
            int r = li >> 4, c4 = (li & 15) * 4;
            int grow = row0 + r;
            __half2 h0, h1;
            if (grow < N_NODES) {
                if (XKIND == 0) {
                    float4 xv = ((const float4*)Xv)[(size_t)grow * 16 + (li & 15)];
                    h0 = __floats2half2_rn(xv.x, xv.y);
                    h1 = __floats2half2_rn(xv.z, xv.w);
                } else {
                    uint2 pk = ((const uint2*)Xv)[(size_t)grow * 16 + (li & 15)];
                    h0 = *(__half2*)&pk.x;
                    h1 = *(__half2*)&pk.y;
                }
            } else {
                h0 = __floats2half2_rn(0.f, 0.f);
                h1 = h0;
            }
            *(__half2*)&Xs[r][c4]     = h0;
            *(__half2*)&Xs[r][c4 + 2] = h1;
        }
        __syncthreads();

        float d[4][4];
        #pragma unroll
        for (int j = 0; j < 4; j++)
            #pragma unroll
            for (int k = 0; k < 4; k++) d[j][k] = 0.f;

        #pragma unroll
        for (int kk = 0; kk < 4; kk++) {
            uint32_t a0, a1, a2, a3;
            uint32_t addrA = smem_u32(&Xs[rt * 16 + (lane & 15)][kk * 16 + ((lane >> 4) << 3)]);
            asm volatile("ldmatrix.sync.aligned.m8n8.x4.shared.b16 {%0,%1,%2,%3}, [%4];"
                         : "=r"(a0), "=r"(a1), "=r"(a2), "=r"(a3) : "r"(addrA));
            #pragma unroll
            for (int jj = 0; jj < 2; jj++) {
                uint32_t q0, q1, q2, q3;
                uint32_t addrB = smem_u32(&Wh[kk * 16 + (lane & 15)]
                                             [ch * 32 + jj * 16 + ((lane >> 4) << 3)]);
                asm volatile("ldmatrix.sync.aligned.m8n8.x4.trans.shared.b16 {%0,%1,%2,%3}, [%4];"
                             : "=r"(q0), "=r"(q1), "=r"(q2), "=r"(q3) : "r"(addrB));
                int j0 = jj * 2, j1 = jj * 2 + 1;
                asm volatile("mma.sync.aligned.m16n8k16.row.col.f32.f16.f16.f32 "
                             "{%0,%1,%2,%3}, {%4,%5,%6,%7}, {%8,%9}, {%0,%1,%2,%3};"
                             : "+f"(d[j0][0]), "+f"(d[j0][1]), "+f"(d[j0][2]), "+f"(d[j0][3])
                             : "r"(a0), "r"(a1), "r"(a2), "r"(a3), "r"(q0), "r"(q1));
                asm volatile("mma.sync.aligned.m16n8k16.row.col.f32.f16.f16.f32 "
                             "{%0,%1,%2,%3}, {%4,%5,%6,%7}, {%8,%9}, {%0,%1,%2,%3};"
                             : "+f"(d[j1][0]), "+f"(d[j1][1]), "+f"(d[j1][2]), "+f"(d[j1][3])
                             : "r"(a0), "r"(a1), "r"(a2), "r"(a3), "r"(q2), "r"(q3));
            }
        }

        int r0 = rt * 16 + (lane >> 2);
        int g0 = row0 + r0, g1 = g0 + 8;
        float dv0 = 1.f, dv1 = 1.f;
        if (DINV) {
            dv0 = (g0 < N_NODES) ? g_dinv[g0] : 0.f;
            dv1 = (g1 < N_NODES) ? g_dinv[g1] : 0.f;
        }
        #pragma unroll
        for (int j = 0; j < 4; j++) {
            int c = ch * 32 + j * 8 + (lane & 3) * 2;
            if (g0 < N_NODES)
                *(__half2*)&g_H[(size_t)g0 * 64 + c] = __floats2half2_rn(d[j][0] * dv0, d[j][1] * dv0);
            if (g1 < N_NODES)
                *(__half2*)&g_H[(size_t)g1 * 64 + c] = __floats2half2_rn(d[j][2] * dv1, d[j][3] * dv1);
        }
        __syncthreads();
    }
}

// ---------------- agg phase: cp.async staged gather, 2 rows/warp ---------------
// Stage = 8 edges/row x 2 rows = 16 edge-rows x 128B = 2KB; 2 stages/warp.
// cp.async.cg 16B/lane: 1 instr covers 4 edges. Zero pad row absorbs tails.
__device__ __forceinline__ void agg_phase(const float* __restrict__ b,
                                          void* __restrict__ outp,
                                          int relu, int outHalf,
                                          int lane, int wid, int bid,
                                          char* s_mem) {
    const char* HB = (const char*)g_H;
    uint32_t aggbase = smem_u32(s_mem) + wid * 4096;   // 2 stages x 2KB per warp
    int sub = lane & 7;                                 // 16B sub-chunk in row
    int eidx0 = lane >> 3;                              // 0..3

    for (int rg = bid; rg < NRG2; rg += NBLK) {
        int rowA = rg * 16 + wid * 2;
        int rowB = rowA + 1;

        int sA = g_rowstart[rowA];
        int eA = g_rowstart[rowA + 1];
        int sB = eA;
        int eB = g_rowstart[rowB + 1];
        int dmax = max(eA - sA, eB - sB);
        int nch = (dmax + 7) >> 3;                      // 8 edges/row per chunk

        auto issue = [&](int off, int stg) {
            int iA0 = sA + off + eidx0, iA1 = iA0 + 4;
            int iB0 = sB + off + eidx0, iB1 = iB0 + 4;
            int uA0 = (iA0 < eA) ? __ldg(&g_csrsrc[iA0]) : N_NODES;
            int uA1 = (iA1 < eA) ? __ldg(&g_csrsrc[iA1]) : N_NODES;
            int uB0 = (iB0 < eB) ? __ldg(&g_csrsrc[iB0]) : N_NODES;
            int uB1 = (iB1 < eB) ? __ldg(&g_csrsrc[iB1]) : N_NODES;
            uint32_t base = aggbase + stg * 2048 + sub * 16;
            cp16(base + (eidx0     ) * 128, HB + (size_t)uA0 * 128 + sub * 16);
            cp16(base + (eidx0 +  4) * 128, HB + (size_t)uA1 * 128 + sub * 16);
            cp16(base + (eidx0 +  8) * 128, HB + (size_t)uB0 * 128 + sub * 16);
            cp16(base + (eidx0 + 12) * 128, HB + (size_t)uB1 * 128 + sub * 16);
            asm volatile("cp.async.commit_group;" ::: "memory");
        };

        float2 accA = make_float2(0.f, 0.f);
        float2 accB = make_float2(0.f, 0.f);

        int inflight = 0;
        issue(0, 0); inflight = 1;
        if (nch > 1) { issue(8, 1); inflight = 2; }

        for (int c = 0; c < nch; c++) {
            if (inflight == 2)
                asm volatile("cp.async.wait_group 1;" ::: "memory");
            else
                asm volatile("cp.async.wait_group 0;" ::: "memory");
            __syncwarp();
            // consume stage c&1
            const __half2* buf = (const __half2*)(s_mem + wid * 4096 + (c & 1) * 2048);
            __half2 pa = __hadd2(buf[0 * 32 + lane], buf[1 * 32 + lane]);
            __half2 pb = __hadd2(buf[2 * 32 + lane], buf[3 * 32 + lane]);
            __half2 pc = __hadd2(buf[4 * 32 + lane], buf[5 * 32 + lane]);
            __half2 pd = __hadd2(buf[6 * 32 + lane], buf[7 * 32 + lane]);
            float2 f0 = __half22float2(pa), f1 = __half22float2(pb);
            float2 f2 = __half22float2(pc), f3 = __half22float2(pd);
            accA.x += (f0.x + f1.x) + (f2.x + f3.x);
            accA.y += (f0.y + f1.y) + (f2.y + f3.y);
            pa = __hadd2(buf[ 8 * 32 + lane], buf[ 9 * 32 + lane]);
            pb = __hadd2(buf[10 * 32 + lane], buf[11 * 32 + lane]);
            pc = __hadd2(buf[12 * 32 + lane], buf[13 * 32 + lane]);
            pd = __hadd2(buf[14 * 32 + lane], buf[15 * 32 + lane]);
            f0 = __half22float2(pa); f1 = __half22float2(pb);
            f2 = __half22float2(pc); f3 = __half22float2(pd);
            accB.x += (f0.x + f1.x) + (f2.x + f3.x);
            accB.y += (f0.y + f1.y) + (f2.y + f3.y);
            inflight--;
            int nxt = c + 2;
            if (nxt < nch) {
                __syncwarp();
                issue(nxt * 8, c & 1);
                inflight++;
            }
        }

        const __half2* H2 = (const __half2*)g_H;
        float dvA = g_dinv[rowA];
        float dvB = g_dinv[rowB];
        float2 hA = __half22float2(H2[(size_t)rowA * 32 + lane]);
        float2 hB = __half22float2(H2[(size_t)rowB * 32 + lane]);
        float2 bv = ((const float2*)b)[lane];
        accA.x = fmaf(accA.x + hA.x, dvA, bv.x);
        accA.y = fmaf(accA.y + hA.y, dvA, bv.y);
        accB.x = fmaf(accB.x + hB.x, dvB, bv.x);
        accB.y = fmaf(accB.y + hB.y, dvB, bv.y);
        if (relu) {
            accA.x = fmaxf(accA.x, 0.f);  accA.y = fmaxf(accA.y, 0.f);
            accB.x = fmaxf(accB.x, 0.f);  accB.y = fmaxf(accB.y, 0.f);
        }
        if (outHalf) {
            *(__half2*)((__half*)outp + (size_t)rowA * 64 + lane * 2) =
                __floats2half2_rn(accA.x, accA.y);
            *(__half2*)((__half*)outp + (size_t)rowB * 64 + lane * 2) =
                __floats2half2_rn(accB.x, accB.y);
        } else {
            ((float2*)((float*)outp + (size_t)rowA * 64))[lane] = accA;
            ((float2*)((float*)outp + (size_t)rowB * 64))[lane] = accB;
        }
    }
}

// ---------------- the megakernel ----------------------------------------------
__global__ __launch_bounds__(TPB, 4) void mega_kernel(
    const float* __restrict__ x,
    const int*   __restrict__ src,
    const int*   __restrict__ dst,
    const float* __restrict__ W1, const float* __restrict__ b1,
    const float* __restrict__ W2, const float* __restrict__ b2,
    const float* __restrict__ W3, const float* __restrict__ b3,
    float* __restrict__ out)
{
    // unioned smem: gemm tiles (18.4KB) OR agg staging (32KB); phases barrier-separated
    __shared__ __align__(16) char s_mem[32768];
    __shared__ int s_wsum[8];
    __shared__ int s_prefix;

    __half (*Xs)[72] = (__half(*)[72])s_mem;
    __half (*Wh)[72] = (__half(*)[72])(s_mem + 64 * 72 * 2);

    int tid = threadIdx.x;
    int bid = blockIdx.x;
    int lane = tid & 31, wid = tid >> 5;

    // ---- phase 0: degree histogram + RAW gemm1 (T = X@W1) ----
    if (bid == 0 && tid < 16)
        ((uint2*)(g_H + (size_t)N_NODES * FEAT))[tid] = make_uint2(0u, 0u);
    for (int e4 = bid * TPB + tid; e4 < NE4; e4 += NBLK * TPB) {
        int4 d = __ldg(&((const int4*)dst)[e4]);
        atomicAdd(&g_zr[d.x], 1);
        atomicAdd(&g_zr[d.y], 1);
        atomicAdd(&g_zr[d.z], 1);
        atomicAdd(&g_zr[d.w], 1);
    }
    gemm_phase_mma<0, 0>(x, W1, tid, bid, Xs, Wh);
    grid_barrier();

    // ---- phase 1: lookback scan -> rowstart, cursor, dinv ----
    if (bid < SCAN_NBLOCKS) {
        int idx0 = bid * SCAN_CHUNK + tid * SCAN_PT;
        int v[SCAN_PT];
        int sum = 0;
        #pragma unroll
        for (int j = 0; j < SCAN_PT; j++) {
            int i = idx0 + j;
            v[j] = (i < N_NODES) ? g_zr[i] : 0;
            sum += v[j];
        }
        int xsc = sum;
        #pragma unroll
        for (int d2 = 1; d2 < 32; d2 <<= 1) {
            int t2 = __shfl_up_sync(0xFFFFFFFFu, xsc, d2);
            if (lane >= d2) xsc += t2;
        }
        if (lane == 31) s_wsum[wid] = xsc;
        __syncthreads();
        if (wid == 0) {
            int sv = (lane < 8) ? s_wsum[lane] : 0;
            #pragma unroll
            for (int d2 = 1; d2 < 8; d2 <<= 1) {
                int t2 = __shfl_up_sync(0xFFFFFFFFu, sv, d2);
                if (lane >= d2) sv += t2;
            }
            if (lane < 8) s_wsum[lane] = sv;
        }
        __syncthreads();
        int thr_excl = (xsc - sum) + (wid ? s_wsum[wid - 1] : 0);
        int blk_total = s_wsum[7];

        if (tid == 0) {
            int pre = 0;
            if (bid > 0) {
                int f;
                do { f = atomicAdd(&g_zr[N_NODES + bid - 1], 0); } while (f == 0);
                pre = f & FLAG_MASK;
            }
            __threadfence();
            atomicExch(&g_zr[N_NODES + bid], FLAG_VALID | (pre + blk_total));
            s_prefix = pre;
            if (bid == SCAN_NBLOCKS - 1) g_rowstart[N_NODES] = pre + blk_total;
        }
        __syncthreads();
        int run = s_prefix + thr_excl;
        #pragma unroll
        for (int j = 0; j < SCAN_PT; j++) {
            int i = idx0 + j;
            if (i < N_NODES) {
                g_rowstart[i] = run;
                g_cursor[i]   = run;
                g_dinv[i] = rsqrtf((float)v[j] + 1.0f);
            }
            run += v[j];
        }
    }
    grid_barrier();

    // ---- phase 2: csr build + in-place H scale (H = dinv .* T) ----
    for (int e4 = bid * TPB + tid; e4 < NE4; e4 += NBLK * TPB) {
        int4 s4 = __ldg(&((const int4*)src)[e4]);
        int4 d4 = __ldg(&((const int4*)dst)[e4]);
        g_csrsrc[atomicAdd(&g_cursor[d4.x], 1)] = s4.x;
        g_csrsrc[atomicAdd(&g_cursor[d4.y], 1)] = s4.y;
        g_csrsrc[atomicAdd(&g_cursor[d4.z], 1)] = s4.z;
        g_csrsrc[atomicAdd(&g_cursor[d4.w], 1)] = s4.w;
    }
    {
        __half2* H2 = (__half2*)g_H;
        for (int i = bid * TPB + tid; i < NH2; i += NBLK * TPB) {
            int row = i >> 5;
            float dv = g_dinv[row];
            float2 vf = __half22float2(H2[i]);
            H2[i] = __floats2half2_rn(vf.x * dv, vf.y * dv);
        }
    }
    grid_barrier();

    // ---- layers ----
    agg_phase(b1, g_Ah, 1, 1, lane, wid, bid, s_mem);
    grid_barrier();
    gemm_phase_mma<1, 1>(g_Ah, W2, tid, bid, Xs, Wh);
    grid_barrier();
    agg_phase(b2, g_Ah, 1, 1, lane, wid, bid, s_mem);
    grid_barrier();
    gemm_phase_mma<1, 1>(g_Ah, W3, tid, bid, Xs, Wh);
    grid_barrier();
    agg_phase(b3, out, 0, 0, lane, wid, bid, s_mem);
}

// ---------------- launch ------------------------------------------------------

extern "C" void kernel_launch(void* const* d_in, const int* in_sizes, int n_in,
                              void* d_out, int out_size) {
    const float* x   = (const float*)d_in[0];
    const int*   ei  = (const int*)d_in[1];
    const float* W1  = (const float*)d_in[2];
    const float* b1  = (const float*)d_in[3];
    const float* W2  = (const float*)d_in[4];
    const float* b2  = (const float*)d_in[5];
    const float* W3  = (const float*)d_in[6];
    const float* b3  = (const float*)d_in[7];
    float* out = (float*)d_out;

    const int* src = ei;
    const int* dst = ei + N_EDGES;

    void* zr_ptr = nullptr;
    cudaGetSymbolAddress(&zr_ptr, g_zr);
    cudaMemsetAsync(zr_ptr, 0, sizeof(int) * (N_NODES + 64));

    mega_kernel<<<NBLK, TPB>>>(x, src, dst, W1, b1, W2, b2, W3, b3, out);

    (void)in_sizes; (void)n_in; (void)out_size;
}

// round 17
// speedup vs baseline: 2.3511x; 2.3511x over previous
#include <cuda_runtime.h>
#include <cuda_fp16.h>
#include <cstdint>

#define N_NODES 100000
#define N_EDGES 1600000
#define FEAT 64
#define TPB 256
#define NBLK 592                              // 148 SMs x 4 blocks, co-resident
#define NTILE ((N_NODES + 63) / 64)           // 1563 gemm tiles
#define NE4 (N_EDGES / 4)                     // 400000
#define NRG2 (N_NODES / 16)                   // 6250 row-pair groups
#define NH2 (N_NODES * 32)                    // half2 words in H

#define SCAN_PT 16
#define SCAN_CHUNK (TPB * SCAN_PT)            // 4096
#define SCAN_NBLOCKS ((N_NODES + SCAN_CHUNK - 1) / SCAN_CHUNK)   // 25
#define FLAG_VALID (1 << 30)
#define FLAG_MASK  (FLAG_VALID - 1)

// ---------------- scratch (static device globals: allocation-free) ----------
// H' = dinv * (X@W), fp16, ONE zero pad row at index N_NODES.
__device__ __half g_H[(N_NODES + 1) * FEAT];
__device__ __half g_Ah[N_NODES * FEAT];       // activations, fp16 storage
__device__ float  g_dinv[N_NODES];
__device__ int    g_rowstart[N_NODES + 1];
__device__ int    g_cursor[N_NODES];
__device__ int    g_csrsrc[N_EDGES];          // src-only CSR (norm folded into H')
__device__ int    g_zr[N_NODES + 64];         // deg + lookback flags (one memset)
__device__ unsigned g_barTicket = 0;          // monotone grid barrier (replay-safe)

__device__ __forceinline__ uint32_t smem_u32(const void* p) {
    return (uint32_t)__cvta_generic_to_shared(p);
}

// ---- grid-wide barrier ----
__device__ __forceinline__ void grid_barrier() {
    __syncthreads();
    if (threadIdx.x == 0) {
        __threadfence();
        unsigned old = atomicAdd(&g_barTicket, 1u);
        unsigned target = (old / NBLK + 1u) * NBLK;
        while (atomicAdd(&g_barTicket, 0u) < target) __nanosleep(64);
        __threadfence();
    }
    __syncthreads();
}

// ---------------- tensor-core gemm ---------------------------------------------
template<int XKIND, int DINV>
__device__ __forceinline__ void gemm_phase_mma(const void* Xv,
                                               const float* __restrict__ W,
                                               int tid, int bid,
                                               __half (*Xs)[72], __half (*Wh)[72]) {
    {
        const float4* W4 = (const float4*)W;
        #pragma unroll
        for (int i = 0; i < 4; i++) {
            int li = tid + 256 * i;
            int r = li >> 4, c4 = (li & 15) * 4;
            float4 w = W4[li];
            *(__half2*)&Wh[r][c4]     = __floats2half2_rn(w.x, w.y);
            *(__half2*)&Wh[r][c4 + 2] = __floats2half2_rn(w.z, w.w);
        }
    }
    int lane = tid & 31, w8 = tid >> 5;
    int rt = w8 & 3;
    int ch = w8 >> 2;

    for (int t = bid; t < NTILE; t += NBLK) {
        int row0 = t * 64;
        #pragma unroll
        for (int i = 0; i < 4; i++) {
            int li = tid + 256 * i;
            int r = li >> 4, c4 = (li & 15) * 4;
            int grow = row0 + r;
            __half2 h0, h1;
            if (grow < N_NODES) {
                if (XKIND == 0) {
                    float4 xv = ((const float4*)Xv)[(size_t)grow * 16 + (li & 15)];
                    h0 = __floats2half2_rn(xv.x, xv.y);
                    h1 = __floats2half2_rn(xv.z, xv.w);
                } else {
                    uint2 pk = ((const uint2*)Xv)[(size_t)grow * 16 + (li & 15)];
                    h0 = *(__half2*)&pk.x;
                    h1 = *(__half2*)&pk.y;
                }
            } else {
                h0 = __floats2half2_rn(0.f, 0.f);
                h1 = h0;
            }
            *(__half2*)&Xs[r][c4]     = h0;
            *(__half2*)&Xs[r][c4 + 2] = h1;
        }
        __syncthreads();

        float d[4][4];
        #pragma unroll
        for (int j = 0; j < 4; j++)
            #pragma unroll
            for (int k = 0; k < 4; k++) d[j][k] = 0.f;

        #pragma unroll
        for (int kk = 0; kk < 4; kk++) {
            uint32_t a0, a1, a2, a3;
            uint32_t addrA = smem_u32(&Xs[rt * 16 + (lane & 15)][kk * 16 + ((lane >> 4) << 3)]);
            asm volatile("ldmatrix.sync.aligned.m8n8.x4.shared.b16 {%0,%1,%2,%3}, [%4];"
                         : "=r"(a0), "=r"(a1), "=r"(a2), "=r"(a3) : "r"(addrA));
            #pragma unroll
            for (int jj = 0; jj < 2; jj++) {
                uint32_t q0, q1, q2, q3;
                uint32_t addrB = smem_u32(&Wh[kk * 16 + (lane & 15)]
                                             [ch * 32 + jj * 16 + ((lane >> 4) << 3)]);
                asm volatile("ldmatrix.sync.aligned.m8n8.x4.trans.shared.b16 {%0,%1,%2,%3}, [%4];"
                             : "=r"(q0), "=r"(q1), "=r"(q2), "=r"(q3) : "r"(addrB));
                int j0 = jj * 2, j1 = jj * 2 + 1;
                asm volatile("mma.sync.aligned.m16n8k16.row.col.f32.f16.f16.f32 "
                             "{%0,%1,%2,%3}, {%4,%5,%6,%7}, {%8,%9}, {%0,%1,%2,%3};"
                             : "+f"(d[j0][0]), "+f"(d[j0][1]), "+f"(d[j0][2]), "+f"(d[j0][3])
                             : "r"(a0), "r"(a1), "r"(a2), "r"(a3), "r"(q0), "r"(q1));
                asm volatile("mma.sync.aligned.m16n8k16.row.col.f32.f16.f16.f32 "
                             "{%0,%1,%2,%3}, {%4,%5,%6,%7}, {%8,%9}, {%0,%1,%2,%3};"
                             : "+f"(d[j1][0]), "+f"(d[j1][1]), "+f"(d[j1][2]), "+f"(d[j1][3])
                             : "r"(a0), "r"(a1), "r"(a2), "r"(a3), "r"(q2), "r"(q3));
            }
        }

        int r0 = rt * 16 + (lane >> 2);
        int g0 = row0 + r0, g1 = g0 + 8;
        float dv0 = 1.f, dv1 = 1.f;
        if (DINV) {
            dv0 = (g0 < N_NODES) ? g_dinv[g0] : 0.f;
            dv1 = (g1 < N_NODES) ? g_dinv[g1] : 0.f;
        }
        #pragma unroll
        for (int j = 0; j < 4; j++) {
            int c = ch * 32 + j * 8 + (lane & 3) * 2;
            if (g0 < N_NODES)
                *(__half2*)&g_H[(size_t)g0 * 64 + c] = __floats2half2_rn(d[j][0] * dv0, d[j][1] * dv0);
            if (g1 < N_NODES)
                *(__half2*)&g_H[(size_t)g1 * 64 + c] = __floats2half2_rn(d[j][2] * dv1, d[j][3] * dv1);
        }
        __syncthreads();
    }
}

// ---------------- agg phase: 2 rows/warp + cross-iteration prefetch -----------
// out[i] = dinv[i]*(sum_u H'[u] + H'[i]) + b ; pad gathers hit zero row.
// Next row-pair's rowstart + first csr window are prefetched at the top of the
// current iteration so their latency hides under the current gathers/consume.
__device__ __forceinline__ void agg_phase(const float* __restrict__ b,
                                          void* __restrict__ outp,
                                          int relu, int outHalf,
                                          int lane, int wid, int bid) {
    const __half2* H2 = (const __half2*)g_H;

    // consume one 32-edge window for both rows given per-lane csr values
    auto window = [&](int uuA, int uuB, int cnt, float2& accA, float2& accB) {
        for (int g0 = 0; g0 < cnt; g0 += 8) {
            int uA[8], uB[8];
            #pragma unroll
            for (int j = 0; j < 8; j++) {
                uA[j] = __shfl_sync(0xFFFFFFFFu, uuA, g0 + j);
                uB[j] = __shfl_sync(0xFFFFFFFFu, uuB, g0 + j);
            }
            __half2 vA[8], vB[8];
            #pragma unroll
            for (int j = 0; j < 8; j++)
                vA[j] = H2[(size_t)uA[j] * 32 + lane];
            #pragma unroll
            for (int j = 0; j < 8; j++)
                vB[j] = H2[(size_t)uB[j] * 32 + lane];
            #pragma unroll
            for (int j = 0; j < 8; j += 2) {
                float2 fa = __half22float2(__hadd2(vA[j], vA[j + 1]));
                float2 fb = __half22float2(__hadd2(vB[j], vB[j + 1]));
                accA.x += fa.x;  accA.y += fa.y;
                accB.x += fb.x;  accB.y += fb.y;
            }
        }
    };

    int rg = bid;
    int sA = 0, eA = 0, eB = 0, uuA = N_NODES, uuB = N_NODES;
    if (rg < NRG2) {
        int rowA = rg * 16 + wid * 2;
        int2 se = *(const int2*)&g_rowstart[rowA];   // rowA even -> 8B aligned
        sA = se.x; eA = se.y;
        eB = g_rowstart[rowA + 2];
        int iA = sA + lane, iB = eA + lane;
        uuA = (iA < eA) ? __ldg(&g_csrsrc[iA]) : N_NODES;
        uuB = (iB < eB) ? __ldg(&g_csrsrc[iB]) : N_NODES;
    }

    for (; rg < NRG2; rg += NBLK) {
        int rowA = rg * 16 + wid * 2;
        int rowB = rowA + 1;
        int sAc = sA, eAc = eA, eBc = eB;
        int uuAc = uuA, uuBc = uuB;

        // prefetch NEXT iteration (off critical path; consumed one iter later)
        int rgn = rg + NBLK;
        if (rgn < NRG2) {
            int rowAn = rgn * 16 + wid * 2;
            int2 se = *(const int2*)&g_rowstart[rowAn];
            sA = se.x; eA = se.y;
            eB = g_rowstart[rowAn + 2];
            int iA = sA + lane, iB = eA + lane;
            uuA = (iA < eA) ? __ldg(&g_csrsrc[iA]) : N_NODES;
            uuB = (iB < eB) ? __ldg(&g_csrsrc[iB]) : N_NODES;
        }

        int sBc = eAc;
        int dmax = max(eAc - sAc, eBc - sBc);
        float2 accA = make_float2(0.f, 0.f);
        float2 accB = make_float2(0.f, 0.f);

        // first window: csr already in registers
        int cnt0 = (dmax < 32) ? dmax : 32;
        window(uuAc, uuBc, cnt0, accA, accB);

        // rare tail: degree > 32
        for (int off = 32; off < dmax; off += 32) {
            int iA = sAc + off + lane;
            int iB = sBc + off + lane;
            int wA = (iA < eAc) ? __ldg(&g_csrsrc[iA]) : N_NODES;
            int wB = (iB < eBc) ? __ldg(&g_csrsrc[iB]) : N_NODES;
            int cnt = dmax - off;
            if (cnt > 32) cnt = 32;
            window(wA, wB, cnt, accA, accB);
        }

        float dvA = g_dinv[rowA];
        float dvB = g_dinv[rowB];
        float2 hA = __half22float2(H2[(size_t)rowA * 32 + lane]);
        float2 hB = __half22float2(H2[(size_t)rowB * 32 + lane]);
        float2 bv = ((const float2*)b)[lane];
        accA.x = fmaf(accA.x + hA.x, dvA, bv.x);
        accA.y = fmaf(accA.y + hA.y, dvA, bv.y);
        accB.x = fmaf(accB.x + hB.x, dvB, bv.x);
        accB.y = fmaf(accB.y + hB.y, dvB, bv.y);
        if (relu) {
            accA.x = fmaxf(accA.x, 0.f);  accA.y = fmaxf(accA.y, 0.f);
            accB.x = fmaxf(accB.x, 0.f);  accB.y = fmaxf(accB.y, 0.f);
        }
        if (outHalf) {
            *(__half2*)((__half*)outp + (size_t)rowA * 64 + lane * 2) =
                __floats2half2_rn(accA.x, accA.y);
            *(__half2*)((__half*)outp + (size_t)rowB * 64 + lane * 2) =
                __floats2half2_rn(accB.x, accB.y);
        } else {
            ((float2*)((float*)outp + (size_t)rowA * 64))[lane] = accA;
            ((float2*)((float*)outp + (size_t)rowB * 64))[lane] = accB;
        }
    }
}

// ---------------- the megakernel ----------------------------------------------
__global__ __launch_bounds__(TPB, 4) void mega_kernel(
    const float* __restrict__ x,
    const int*   __restrict__ src,
    const int*   __restrict__ dst,
    const float* __restrict__ W1, const float* __restrict__ b1,
    const float* __restrict__ W2, const float* __restrict__ b2,
    const float* __restrict__ W3, const float* __restrict__ b3,
    float* __restrict__ out)
{
    __shared__ __half Xs[64][72];
    __shared__ __half Wh[64][72];
    __shared__ int    s_wsum[8];
    __shared__ int    s_prefix;

    int tid = threadIdx.x;
    int bid = blockIdx.x;
    int lane = tid & 31, wid = tid >> 5;

    // ---- phase 0: degree histogram + RAW gemm1 (T = X@W1) ----
    if (bid == 0 && tid < 16)
        ((uint2*)(g_H + (size_t)N_NODES * FEAT))[tid] = make_uint2(0u, 0u);
    for (int e4 = bid * TPB + tid; e4 < NE4; e4 += NBLK * TPB) {
        int4 d = __ldg(&((const int4*)dst)[e4]);
        atomicAdd(&g_zr[d.x], 1);
        atomicAdd(&g_zr[d.y], 1);
        atomicAdd(&g_zr[d.z], 1);
        atomicAdd(&g_zr[d.w], 1);
    }
    gemm_phase_mma<0, 0>(x, W1, tid, bid, Xs, Wh);
    grid_barrier();

    // ---- phase 1: lookback scan -> rowstart, cursor, dinv ----
    if (bid < SCAN_NBLOCKS) {
        int idx0 = bid * SCAN_CHUNK + tid * SCAN_PT;
        int v[SCAN_PT];
        int sum = 0;
        #pragma unroll
        for (int j = 0; j < SCAN_PT; j++) {
            int i = idx0 + j;
            v[j] = (i < N_NODES) ? g_zr[i] : 0;
            sum += v[j];
        }
        int xsc = sum;
        #pragma unroll
        for (int d2 = 1; d2 < 32; d2 <<= 1) {
            int t2 = __shfl_up_sync(0xFFFFFFFFu, xsc, d2);
            if (lane >= d2) xsc += t2;
        }
        if (lane == 31) s_wsum[wid] = xsc;
        __syncthreads();
        if (wid == 0) {
            int sv = (lane < 8) ? s_wsum[lane] : 0;
            #pragma unroll
            for (int d2 = 1; d2 < 8; d2 <<= 1) {
                int t2 = __shfl_up_sync(0xFFFFFFFFu, sv, d2);
                if (lane >= d2) sv += t2;
            }
            if (lane < 8) s_wsum[lane] = sv;
        }
        __syncthreads();
        int thr_excl = (xsc - sum) + (wid ? s_wsum[wid - 1] : 0);
        int blk_total = s_wsum[7];

        if (tid == 0) {
            int pre = 0;
            if (bid > 0) {
                int f;
                do { f = atomicAdd(&g_zr[N_NODES + bid - 1], 0); } while (f == 0);
                pre = f & FLAG_MASK;
            }
            __threadfence();
            atomicExch(&g_zr[N_NODES + bid], FLAG_VALID | (pre + blk_total));
            s_prefix = pre;
            if (bid == SCAN_NBLOCKS - 1) g_rowstart[N_NODES] = pre + blk_total;
        }
        __syncthreads();
        int run = s_prefix + thr_excl;
        #pragma unroll
        for (int j = 0; j < SCAN_PT; j++) {
            int i = idx0 + j;
            if (i < N_NODES) {
                g_rowstart[i] = run;
                g_cursor[i]   = run;
                g_dinv[i] = rsqrtf((float)v[j] + 1.0f);
            }
            run += v[j];
        }
    }
    grid_barrier();

    // ---- phase 2: csr build + in-place H scale (H = dinv .* T) ----
    for (int e4 = bid * TPB + tid; e4 < NE4; e4 += NBLK * TPB) {
        int4 s4 = __ldg(&((const int4*)src)[e4]);
        int4 d4 = __ldg(&((const int4*)dst)[e4]);
        g_csrsrc[atomicAdd(&g_cursor[d4.x], 1)] = s4.x;
        g_csrsrc[atomicAdd(&g_cursor[d4.y], 1)] = s4.y;
        g_csrsrc[atomicAdd(&g_cursor[d4.z], 1)] = s4.z;
        g_csrsrc[atomicAdd(&g_cursor[d4.w], 1)] = s4.w;
    }
    {
        __half2* H2 = (__half2*)g_H;
        for (int i = bid * TPB + tid; i < NH2; i += NBLK * TPB) {
            int row = i >> 5;
            float dv = g_dinv[row];
            float2 vf = __half22float2(H2[i]);
            H2[i] = __floats2half2_rn(vf.x * dv, vf.y * dv);
        }
    }
    grid_barrier();

    // ---- layers ----
    agg_phase(b1, g_Ah, 1, 1, lane, wid, bid);
    grid_barrier();
    gemm_phase_mma<1, 1>(g_Ah, W2, tid, bid, Xs, Wh);
    grid_barrier();
    agg_phase(b2, g_Ah, 1, 1, lane, wid, bid);
    grid_barrier();
    gemm_phase_mma<1, 1>(g_Ah, W3, tid, bid, Xs, Wh);
    grid_barrier();
    agg_phase(b3, out, 0, 0, lane, wid, bid);
}

// ---------------- launch ------------------------------------------------------

extern "C" void kernel_launch(void* const* d_in, const int* in_sizes, int n_in,
                              void* d_out, int out_size) {
    const float* x   = (const float*)d_in[0];
    const int*   ei  = (const int*)d_in[1];
    const float* W1  = (const float*)d_in[2];
    const float* b1  = (const float*)d_in[3];
    const float* W2  = (const float*)d_in[4];
    const float* b2  = (const float*)d_in[5];
    const float* W3  = (const float*)d_in[6];
    const float* b3  = (const float*)d_in[7];
    float* out = (float*)d_out;

    const int* src = ei;
    const int* dst = ei + N_EDGES;

    void* zr_ptr = nullptr;
    cudaGetSymbolAddress(&zr_ptr, g_zr);
    cudaMemsetAsync(zr_ptr, 0, sizeof(int) * (N_NODES + 64));

    mega_kernel<<<NBLK, TPB>>>(x, src, dst, W1, b1, W2, b2, W3, b3, out);

    (void)in_sizes; (void)n_in; (void)out_size;
}